// round 13
// baseline (speedup 1.0000x reference)
#include <cuda_runtime.h>
#include <cuda_fp16.h>
#include <math.h>

#define NBRN  12
#define M_ROWS 18432
#define BA_ROWS 1536
#define H1    512
#define H2    128
#define FN    64

// ---------------- scratch ----------------
// base weights (fp16 hi/lo of w), noise planes fp16(2^b*u_b), plane-7 lo residual
__device__ __half g_W1Nbh[H1*64],  g_W1Nbl[H1*64],  g_W1Nn[H1*512],  g_W1Nn7[H1*64];
__device__ __half g_W1Ebh[H1*64],  g_W1Ebl[H1*64],  g_W1En[H1*512],  g_W1En7[H1*64];
__device__ __half g_W2bh[H2*512],  g_W2bl[H2*512],  g_W2n[H2*4096],  g_W2n7[H2*512];
__device__ float  g_C1N[H1], g_C1E[H1], g_C2[H2];     // 1024*sum(w) corrections
__device__ float  g_S1[H1], g_S2[H2];
__device__ float  g_zn[BA_ROWS * H1];
__device__ float  g_h[(size_t)M_ROWS * H1];
__device__ float  g_c2[M_ROWS * H2];
__device__ float  g_ns[BA_ROWS * FN];
__device__ float  g_mean[FN], g_var[FN];
__device__ int    g_mn1, g_mx1, g_mn2, g_mx2;

// ---------------- helpers ----------------
__device__ __forceinline__ void atomicMinF(int* a, float v) {
    if (v >= 0.f) atomicMin(a, __float_as_int(v));
    else          atomicMax((unsigned*)a, (unsigned)__float_as_int(v));
}
__device__ __forceinline__ void atomicMaxF(int* a, float v) {
    if (v >= 0.f) atomicMax(a, __float_as_int(v));
    else          atomicMin((unsigned*)a, (unsigned)__float_as_int(v));
}
__device__ __forceinline__ void cp_async16(void* s, const void* g) {
    unsigned sa = (unsigned)__cvta_generic_to_shared(s);
    asm volatile("cp.async.cg.shared.global [%0], [%1], 16;\n" :: "r"(sa), "l"(g));
}
__device__ __forceinline__ void ldmx4(unsigned& r0, unsigned& r1, unsigned& r2, unsigned& r3,
                                      const __half* p) {
    unsigned a = (unsigned)__cvta_generic_to_shared(p);
    asm volatile("ldmatrix.sync.aligned.m8n8.x4.shared.b16 {%0,%1,%2,%3},[%4];"
                 : "=r"(r0), "=r"(r1), "=r"(r2), "=r"(r3) : "r"(a));
}
__device__ __forceinline__ unsigned qz(float x, float mn, float sc) {
    float t = (x - mn) * sc;
    int q = (int)t; q = q < 0 ? 0 : (q > 255 ? 255 : q);
    return (unsigned)q;
}

// ---------------- small kernels ----------------
__global__ void k_init() {
    g_mn1 = 0x7f800000; g_mx1 = (int)0xff800000;
    g_mn2 = 0x7f800000; g_mx2 = (int)0xff800000;
}

#define NODE_N (BA_ROWS * FN)
#define EDGE_N (M_ROWS * 64)
__global__ void k_minmax(const float* __restrict__ node, const float* __restrict__ edge) {
    int idx = blockIdx.x * 256 + threadIdx.x;
    float v = (idx < NODE_N) ? node[idx] : edge[idx - NODE_N];
    float mn = v, mx = v;
    #pragma unroll
    for (int o = 16; o; o >>= 1) {
        mn = fminf(mn, __shfl_xor_sync(~0u, mn, o));
        mx = fmaxf(mx, __shfl_xor_sync(~0u, mx, o));
    }
    __shared__ float smn[8], smx[8];
    int lane = threadIdx.x & 31, w = threadIdx.x >> 5;
    if (lane == 0) { smn[w] = mn; smx[w] = mx; }
    __syncthreads();
    if (threadIdx.x == 0) {
        float bmn = smn[0], bmx = smx[0];
        #pragma unroll
        for (int i = 1; i < 8; i++) { bmn = fminf(bmn, smn[i]); bmx = fmaxf(bmx, smx[i]); }
        atomicMinF(&g_mn1, bmn); atomicMaxF(&g_mx1, bmx);
    }
}

__global__ void k_prep1(const float* __restrict__ cond1, const float* __restrict__ eps1) {
    int o = blockIdx.x, i = threadIdx.x;        // 512 x 128
    float w = cond1[o * 128 + i];
    float aw = fabsf(w) * 0.1f;
    float u[8];
    #pragma unroll
    for (int b = 0; b < 8; b++)
        u[b] = eps1[b * (H1 * 128) + o * 128 + i] * aw;
    __half bh = __float2half_rn(w);
    float bhf = __half2float(bh);
    __half bl = __float2half_rn(w - bhf);
    float blf = __half2float(bl);
    int isn = (i < 64), il = i & 63;
    if (isn) { g_W1Nbh[o * 64 + il] = bh; g_W1Nbl[o * 64 + il] = bl; }
    else     { g_W1Ebh[o * 64 + il] = bh; g_W1Ebl[o * 64 + il] = bl; }
    #pragma unroll
    for (int b = 0; b < 8; b++) {
        __half nh = __float2half_rn((float)(1 << b) * u[b]);
        if (isn) g_W1Nn[o * 512 + b * 64 + il] = nh;
        else     g_W1En[o * 512 + b * 64 + il] = nh;
    }
    float v7 = 128.f * u[7];
    __half h7 = __float2half_rn(v7);
    __half l7 = __float2half_rn(v7 - __half2float(h7));
    if (isn) g_W1Nn7[o * 64 + il] = l7;
    else     g_W1En7[o * 64 + il] = l7;

    float c = 1024.f * (bhf + blf);
    __shared__ float red[128];
    red[i] = w + u[7]; __syncthreads();
    #pragma unroll
    for (int s = 64; s; s >>= 1) { if (i < s) red[i] += red[i + s]; __syncthreads(); }
    if (i == 0) g_S1[o] = red[0];
    __syncthreads();
    red[i] = isn ? c : 0.f; __syncthreads();
    #pragma unroll
    for (int s = 64; s; s >>= 1) { if (i < s) red[i] += red[i + s]; __syncthreads(); }
    if (i == 0) g_C1N[o] = red[0];
    __syncthreads();
    red[i] = isn ? 0.f : c; __syncthreads();
    #pragma unroll
    for (int s = 64; s; s >>= 1) { if (i < s) red[i] += red[i + s]; __syncthreads(); }
    if (i == 0) g_C1E[o] = red[0];
}

__global__ void k_prep2(const float* __restrict__ cond2, const float* __restrict__ eps2) {
    int o = blockIdx.x, t = threadIdx.x;        // 128 x 256
    float sr = 0.f, cc = 0.f;
    for (int i = t; i < H1; i += 256) {
        float w = cond2[o * H1 + i];
        float aw = fabsf(w) * 0.1f;
        sr += cond2[H2 * H1 + o * H1 + i];
        __half bh = __float2half_rn(w);
        float bhf = __half2float(bh);
        __half bl = __float2half_rn(w - bhf);
        cc += 1024.f * (bhf + __half2float(bl));
        g_W2bh[o * 512 + i] = bh; g_W2bl[o * 512 + i] = bl;
        float u7 = 0.f;
        #pragma unroll
        for (int b = 0; b < 8; b++) {
            float u = eps2[b * (H2 * H1) + o * H1 + i] * aw;
            if (b == 7) u7 = u;
            g_W2n[o * 4096 + b * 512 + i] = __float2half_rn((float)(1 << b) * u);
        }
        float v7 = 128.f * u7;
        __half h7 = __float2half_rn(v7);
        g_W2n7[o * 512 + i] = __float2half_rn(v7 - __half2float(h7));
    }
    __shared__ float red[256];
    red[t] = sr; __syncthreads();
    #pragma unroll
    for (int s = 128; s; s >>= 1) { if (t < s) red[t] += red[t + s]; __syncthreads(); }
    if (t == 0) g_S2[o] = red[0];
    __syncthreads();
    red[t] = cc; __syncthreads();
    #pragma unroll
    for (int s = 128; s; s >>= 1) { if (t < s) red[t] += red[t + s]; __syncthreads(); }
    if (t == 0) g_C2[o] = red[0];
}

// ---------------- GEMM: base (Q+1024, w hi/lo) + noise (bit planes) ----------------
// Stages per 64-k slice: 2 base + 8 noise + 1 noise7-lo = 11 (vs 12 before).
// A expanded CTA-wide from q-byte slab into smem (double-buffered), ldmatrix fetch.
// EPI=0: node (M=1536, SC=64) -> g_zn; EPI=1: edge -> g_h; EPI=2: layer2 (SC=512) -> g_c2.
template<int EPI>
__global__ void __launch_bounds__(256) k_tc(const float* __restrict__ node,
                                            const float* __restrict__ edge) {
    constexpr int SC  = (EPI == 2) ? 512 : 64;
    constexpr int N   = (EPI == 2) ? H2 : H1;
    constexpr int SPP = SC / 64;
    constexpr int NSB = 2 * SPP;
    constexpr int NSN = 8 * SPP;
    constexpr int NST = 11 * SPP;
    constexpr int QROWB = SC + 16;
    constexpr int SROW  = 72;
    constexpr int BTILE = 128 * SROW;
    const __half* Wbh = (EPI == 0) ? g_W1Nbh : (EPI == 1) ? g_W1Ebh : g_W2bh;
    const __half* Wbl = (EPI == 0) ? g_W1Nbl : (EPI == 1) ? g_W1Ebl : g_W2bl;
    const __half* Wn  = (EPI == 0) ? g_W1Nn  : (EPI == 1) ? g_W1En  : g_W2n;
    const __half* Wn7 = (EPI == 0) ? g_W1Nn7 : (EPI == 1) ? g_W1En7 : g_W2n7;
    const float*  C   = (EPI == 0) ? g_C1N : (EPI == 1) ? g_C1E : g_C2;
    const float*  S   = (EPI == 2) ? g_S2 : g_S1;
    float* out = (EPI == 0) ? g_zn : (EPI == 1) ? g_h : g_c2;

    extern __shared__ char smraw[];
    __half*        bsm   = (__half*)smraw;          // 3 B tiles
    __half*        asmem = bsm + 3 * BTILE;         // 2 A tiles
    unsigned char* qs    = (unsigned char*)(bsm + 5 * BTILE);  // q slab

    const int tid = threadIdx.x, wid = tid >> 5, lane = tid & 31;
    const int wm = wid >> 1, wn = wid & 1;
    const int g = lane >> 2, ti2 = (lane & 3) * 2;
    const int m0 = blockIdx.y * 128, n0 = blockIdx.x * 128;

    float mn, mx;
    if (EPI == 2) { mn = __int_as_float(g_mn2); mx = __int_as_float(g_mx2); }
    else          { mn = __int_as_float(g_mn1); mx = __int_as_float(g_mx1); }
    float qsc = 255.0f / (mx - mn);

    // ---- phase 1: quantize source slab -> q bytes ----
    constexpr int SEGS = SC / 16;
    #pragma unroll 1
    for (int u = tid; u < 128 * SEGS; u += 256) {
        int r = u / SEGS, seg = u % SEGS;
        const float4* p;
        if (EPI == 0)      p = (const float4*)(node + (m0 + r) * FN + seg * 16);
        else if (EPI == 1) p = (const float4*)(edge + (size_t)(m0 + r) * 64 + seg * 16);
        else               p = (const float4*)(g_h + (size_t)(m0 + r) * H1 + seg * 16);
        uint4 o4;
        unsigned* ow = (unsigned*)&o4;
        #pragma unroll
        for (int j = 0; j < 4; j++) {
            float4 v = p[j];
            ow[j] = qz(v.x, mn, qsc) | (qz(v.y, mn, qsc) << 8) |
                    (qz(v.z, mn, qsc) << 16) | (qz(v.w, mn, qsc) << 24);
        }
        *(uint4*)(qs + r * QROWB + seg * 16) = o4;
    }
    __syncthreads();   // q slab complete before any expandA

    // ---- k-loop ----
    float acc[2][8][4];
    #pragma unroll
    for (int a = 0; a < 2; a++)
        #pragma unroll
        for (int b = 0; b < 8; b++)
            #pragma unroll
            for (int c = 0; c < 4; c++) acc[a][b][c] = 0.f;

    auto aidx = [&](int s) { return (s < NSB) ? (s >> 1) : (SPP + s - NSB); };

    auto loadB = [&](int s) {
        const __half* W; int rs, kofs;
        if (s < NSB)            { int j = s >> 1; W = (s & 1) ? Wbl : Wbh; rs = SC;     kofs = j * 64; }
        else if (s < NSB + NSN) { int s2 = s - NSB; W = Wn;                rs = 8 * SC; kofs = s2 * 64; }
        else                    { int s7 = s - NSB - NSN; W = Wn7;         rs = SC;     kofs = s7 * 64; }
        __half* bs = bsm + (s % 3) * BTILE;
        #pragma unroll
        for (int it2 = 0; it2 < 4; it2++) {
            int cid = tid + it2 * 256;
            int r = cid >> 3, c = (cid & 7) * 8;
            cp_async16(&bs[r * SROW + c], W + (size_t)(n0 + r) * rs + kofs + c);
        }
        asm volatile("cp.async.commit_group;\n");
    };

    // expand A tile for aidx ai into buffer ai&1: base (q+1024) or noise (bit b)
    const int er = tid >> 1, ehf = tid & 1;
    auto expandA = [&](int ai) {
        __half* as2 = asmem + (ai & 1) * BTILE;
        uint4* dst = (uint4*)(as2 + er * SROW + ehf * 32);
        if (ai < SPP) {
            const uint4* q4 = (const uint4*)(qs + er * QROWB + ai * 64 + ehf * 32);
            uint4 a = q4[0], b4 = q4[1];
            uint4 v;
            v.x = __byte_perm(a.x, 0x64646464u, 0x4140); v.y = __byte_perm(a.x, 0x64646464u, 0x4342);
            v.z = __byte_perm(a.y, 0x64646464u, 0x4140); v.w = __byte_perm(a.y, 0x64646464u, 0x4342);
            dst[0] = v;
            v.x = __byte_perm(a.z, 0x64646464u, 0x4140); v.y = __byte_perm(a.z, 0x64646464u, 0x4342);
            v.z = __byte_perm(a.w, 0x64646464u, 0x4140); v.w = __byte_perm(a.w, 0x64646464u, 0x4342);
            dst[1] = v;
            v.x = __byte_perm(b4.x, 0x64646464u, 0x4140); v.y = __byte_perm(b4.x, 0x64646464u, 0x4342);
            v.z = __byte_perm(b4.y, 0x64646464u, 0x4140); v.w = __byte_perm(b4.y, 0x64646464u, 0x4342);
            dst[2] = v;
            v.x = __byte_perm(b4.z, 0x64646464u, 0x4140); v.y = __byte_perm(b4.z, 0x64646464u, 0x4342);
            v.z = __byte_perm(b4.w, 0x64646464u, 0x4140); v.w = __byte_perm(b4.w, 0x64646464u, 0x4342);
            dst[3] = v;
        } else {
            int na = ai - SPP;
            int b  = (na < 8 * SPP) ? (na / SPP) : 7;
            int jj = (na < 8 * SPP) ? (na % SPP) : (na - 8 * SPP);
            const uint4* q4 = (const uint4*)(qs + er * QROWB + jj * 64 + ehf * 32);
            uint4 a = q4[0], b4 = q4[1];
            unsigned qw[8] = {a.x, a.y, a.z, a.w, b4.x, b4.y, b4.z, b4.w};
            #pragma unroll
            for (int j = 0; j < 4; j++) {
                uint4 v;
                unsigned w0 = qw[2 * j], w1 = qw[2 * j + 1];
                v.x = ((w0 >> b) & 1u) * 0x3C00u | ((w0 >> (8 + b)) & 1u) * 0x3C000000u;
                v.y = ((w0 >> (16 + b)) & 1u) * 0x3C00u | ((w0 >> (24 + b)) & 1u) * 0x3C000000u;
                v.z = ((w1 >> b) & 1u) * 0x3C00u | ((w1 >> (8 + b)) & 1u) * 0x3C000000u;
                v.w = ((w1 >> (16 + b)) & 1u) * 0x3C00u | ((w1 >> (24 + b)) & 1u) * 0x3C000000u;
                dst[j] = v;
            }
        }
    };

    const int lm = lane >> 3, lr = lane & 7;
    const int lmbase = (wn * 64 + (lm >> 1) * 8 + lr) * SROW + (lm & 1) * 8;   // B
    const int albase = ((lm & 1) * 8 + lr) * SROW + (lm >> 1) * 8;             // A

    loadB(0);
    loadB(1);
    expandA(0);
    __syncthreads();   // A(0) visible
    #pragma unroll 1
    for (int s = 0; s < NST; s++) {
        if (s + 1 < NST) asm volatile("cp.async.wait_group 1;\n");
        else             asm volatile("cp.async.wait_group 0;\n");
        __syncthreads();                       // prev-iter reads done; B(s) visible
        if (s + 1 < NST && aidx(s + 1) != aidx(s)) expandA(aidx(s + 1));
        if (s + 2 < NST) loadB(s + 2);

        const __half* as2 = asmem + (aidx(s) & 1) * BTILE;
        const __half* bs  = bsm + (s % 3) * BTILE;

        #pragma unroll
        for (int kk = 0; kk < 4; kk++) {
            unsigned af[2][4];
            #pragma unroll
            for (int mt = 0; mt < 2; mt++)
                ldmx4(af[mt][0], af[mt][1], af[mt][2], af[mt][3],
                      as2 + albase + (wm * 32 + mt * 16) * SROW + kk * 16);
            unsigned bq[8][2];
            #pragma unroll
            for (int p = 0; p < 4; p++)
                ldmx4(bq[2 * p][0], bq[2 * p][1], bq[2 * p + 1][0], bq[2 * p + 1][1],
                      bs + lmbase + p * (16 * SROW) + kk * 16);
            #pragma unroll
            for (int mt = 0; mt < 2; mt++)
                #pragma unroll
                for (int nt = 0; nt < 8; nt++)
                    asm volatile(
                        "mma.sync.aligned.m16n8k16.row.col.f32.f16.f16.f32 "
                        "{%0,%1,%2,%3},{%4,%5,%6,%7},{%8,%9},{%0,%1,%2,%3};"
                        : "+f"(acc[mt][nt][0]), "+f"(acc[mt][nt][1]),
                          "+f"(acc[mt][nt][2]), "+f"(acc[mt][nt][3])
                        : "r"(af[mt][0]), "r"(af[mt][1]), "r"(af[mt][2]), "r"(af[mt][3]),
                          "r"(bq[nt][0]), "r"(bq[nt][1]));
        }
    }

    // ---- epilogue ----
    if (EPI == 0) {
        #pragma unroll
        for (int mt = 0; mt < 2; mt++)
            #pragma unroll
            for (int nt = 0; nt < 8; nt++)
                #pragma unroll
                for (int c = 0; c < 4; c++) {
                    int row = m0 + wm * 32 + mt * 16 + g + ((c & 2) << 2);
                    int col = n0 + wn * 64 + nt * 8 + ti2 + (c & 1);
                    out[row * H1 + col] = acc[mt][nt][c] - C[col];
                }
    } else if (EPI == 1) {
        float sc = (mx - mn) * (1.0f / 255.0f);
        float lmn = __int_as_float(0x7f800000), lmx = -lmn;
        #pragma unroll
        for (int mt = 0; mt < 2; mt++)
            #pragma unroll
            for (int nt = 0; nt < 8; nt++)
                #pragma unroll
                for (int c = 0; c < 4; c++) {
                    int row = m0 + wm * 32 + mt * 16 + g + ((c & 2) << 2);
                    int col = n0 + wn * 64 + nt * 8 + ti2 + (c & 1);
                    float z = acc[mt][nt][c] - C[col] + g_zn[(row / NBRN) * H1 + col];
                    float hv = z * sc + mn * S[col];
                    hv = fmaxf(hv, 0.f);
                    out[(size_t)row * N + col] = hv;
                    lmn = fminf(lmn, hv); lmx = fmaxf(lmx, hv);
                }
        #pragma unroll
        for (int o = 16; o; o >>= 1) {
            lmn = fminf(lmn, __shfl_xor_sync(~0u, lmn, o));
            lmx = fmaxf(lmx, __shfl_xor_sync(~0u, lmx, o));
        }
        if (lane == 0) { atomicMinF(&g_mn2, lmn); atomicMaxF(&g_mx2, lmx); }
    } else {
        float sc = (mx - mn) * (1.0f / 255.0f);
        #pragma unroll
        for (int mt = 0; mt < 2; mt++)
            #pragma unroll
            for (int nt = 0; nt < 8; nt++)
                #pragma unroll
                for (int c = 0; c < 4; c++) {
                    int row = m0 + wm * 32 + mt * 16 + g + ((c & 2) << 2);
                    int col = n0 + wn * 64 + nt * 8 + ti2 + (c & 1);
                    out[(size_t)row * N + col] = (acc[mt][nt][c] - C[col]) * sc + mn * S[col];
                }
    }
}

// sigmoid(gate)*tanh(extract)*mask, summed over 12 neighbors
__global__ void k_gate(const float* __restrict__ mask) {
    int idx = blockIdx.x * 256 + threadIdx.x;
    int ba = idx >> 6, j = idx & 63;
    float acc = 0.f;
    #pragma unroll
    for (int nb = 0; nb < NBRN; nb++) {
        int m = ba * NBRN + nb;
        float gv = g_c2[m * H2 + j];
        float ev = g_c2[m * H2 + 64 + j];
        acc += (1.f / (1.f + expf(-gv))) * tanhf(ev) * mask[m];
    }
    g_ns[idx] = acc;
}

// deterministic per-feature BN statistics
__global__ void k_stats() {
    int j = blockIdx.x, t = threadIdx.x;
    __shared__ float red[256];
    __shared__ float mean_s;
    float s = 0.f;
    for (int r = t; r < BA_ROWS; r += 256) s += g_ns[r * FN + j];
    red[t] = s; __syncthreads();
    #pragma unroll
    for (int k = 128; k; k >>= 1) { if (t < k) red[t] += red[t + k]; __syncthreads(); }
    if (t == 0) mean_s = red[0] / (float)BA_ROWS;
    __syncthreads();
    float mean = mean_s, s2 = 0.f;
    for (int r = t; r < BA_ROWS; r += 256) { float d = g_ns[r * FN + j] - mean; s2 += d * d; }
    red[t] = s2; __syncthreads();
    #pragma unroll
    for (int k = 128; k; k >>= 1) { if (t < k) red[t] += red[t + k]; __syncthreads(); }
    if (t == 0) { g_mean[j] = mean; g_var[j] = red[0] / (float)BA_ROWS; }
}

__global__ void k_final(const float* __restrict__ node, const float* __restrict__ gamma,
                        const float* __restrict__ beta, float* __restrict__ out) {
    int idx = blockIdx.x * 256 + threadIdx.x;
    int j = idx & 63;
    float bn = (g_ns[idx] - g_mean[j]) / sqrtf(g_var[j] + 1e-5f) * gamma[j] + beta[j];
    out[idx] = fmaxf(node[idx] + bn, 0.f);
}

// ---------------- launcher ----------------
extern "C" void kernel_launch(void* const* d_in, const int* in_sizes, int n_in,
                              void* d_out, int out_size) {
    const float* node  = (const float*)d_in[0];
    const float* edge  = (const float*)d_in[1];
    const float* maskp = (const float*)d_in[2];
    const float* cond1 = (const float*)d_in[3];
    const float* cond2 = (const float*)d_in[4];
    const float* eps1  = (const float*)d_in[5];
    const float* eps2  = (const float*)d_in[6];
    const float* gamma = (const float*)d_in[7];
    const float* beta  = (const float*)d_in[8];
    float* out = (float*)d_out;

    // smem: 3 B tiles + 2 A tiles + q slab
    const int SMEM01 = 5 * 128 * 72 * 2 + 128 * (64 + 16);    // 102400
    const int SMEM2  = 5 * 128 * 72 * 2 + 128 * (512 + 16);   // 159744
    cudaFuncSetAttribute(k_tc<0>, cudaFuncAttributeMaxDynamicSharedMemorySize, SMEM01);
    cudaFuncSetAttribute(k_tc<1>, cudaFuncAttributeMaxDynamicSharedMemorySize, SMEM01);
    cudaFuncSetAttribute(k_tc<2>, cudaFuncAttributeMaxDynamicSharedMemorySize, SMEM2);

    k_init<<<1, 1>>>();
    k_minmax<<<(NODE_N + EDGE_N) / 256, 256>>>(node, edge);
    k_prep1<<<H1, 128>>>(cond1, eps1);
    k_prep2<<<H2, 256>>>(cond2, eps2);
    k_tc<0><<<dim3(H1 / 128, BA_ROWS / 128), 256, SMEM01>>>(node, edge);
    k_tc<1><<<dim3(H1 / 128, M_ROWS / 128), 256, SMEM01>>>(node, edge);
    k_tc<2><<<dim3(1, M_ROWS / 128), 256, SMEM2>>>(nullptr, nullptr);
    k_gate<<<(BA_ROWS * FN) / 256, 256>>>(maskp);
    k_stats<<<FN, 256>>>();
    k_final<<<(BA_ROWS * FN) / 256, 256>>>(node, gamma, beta, out);
}

// round 14
// speedup vs baseline: 1.0074x; 1.0074x over previous
#include <cuda_runtime.h>
#include <cuda_fp16.h>
#include <math.h>

#define NBRN  12
#define M_ROWS 18432
#define BA_ROWS 1536
#define H1    512
#define H2    128
#define FN    64

// ---------------- scratch ----------------
__device__ __half g_W1Nbh[H1*64],  g_W1Nbl[H1*64],  g_W1Nn[H1*512],  g_W1Nn7[H1*64];
__device__ __half g_W1Ebh[H1*64],  g_W1Ebl[H1*64],  g_W1En[H1*512],  g_W1En7[H1*64];
__device__ __half g_W2bh[H2*512],  g_W2bl[H2*512],  g_W2n[H2*4096],  g_W2n7[H2*512];
__device__ float  g_C1N[H1], g_C1E[H1], g_C2[H2];     // 1024*sum(w) corrections
__device__ float  g_S1[H1], g_S2[H2];
__device__ float  g_zn[BA_ROWS * H1];
__device__ float  g_h[(size_t)M_ROWS * H1];
__device__ float  g_c2[M_ROWS * H2];
__device__ float  g_ns[BA_ROWS * FN];
__device__ float  g_mean[FN], g_var[FN];
__device__ int    g_mn1, g_mx1, g_mn2, g_mx2;

// ---------------- helpers ----------------
__device__ __forceinline__ void atomicMinF(int* a, float v) {
    if (v >= 0.f) atomicMin(a, __float_as_int(v));
    else          atomicMax((unsigned*)a, (unsigned)__float_as_int(v));
}
__device__ __forceinline__ void atomicMaxF(int* a, float v) {
    if (v >= 0.f) atomicMax(a, __float_as_int(v));
    else          atomicMin((unsigned*)a, (unsigned)__float_as_int(v));
}
__device__ __forceinline__ void cp_async16(void* s, const void* g) {
    unsigned sa = (unsigned)__cvta_generic_to_shared(s);
    asm volatile("cp.async.cg.shared.global [%0], [%1], 16;\n" :: "r"(sa), "l"(g));
}
__device__ __forceinline__ void ldmx4(unsigned& r0, unsigned& r1, unsigned& r2, unsigned& r3,
                                      const __half* p) {
    unsigned a = (unsigned)__cvta_generic_to_shared(p);
    asm volatile("ldmatrix.sync.aligned.m8n8.x4.shared.b16 {%0,%1,%2,%3},[%4];"
                 : "=r"(r0), "=r"(r1), "=r"(r2), "=r"(r3) : "r"(a));
}
__device__ __forceinline__ unsigned qz(float x, float mn, float sc) {
    float t = (x - mn) * sc;
    int q = (int)t; q = q < 0 ? 0 : (q > 255 ? 255 : q);
    return (unsigned)q;
}

// ---------------- small kernels ----------------
__global__ void k_init() {
    g_mn1 = 0x7f800000; g_mx1 = (int)0xff800000;
    g_mn2 = 0x7f800000; g_mx2 = (int)0xff800000;
}

#define NODE_N (BA_ROWS * FN)
#define EDGE_N (M_ROWS * 64)
__global__ void k_minmax(const float* __restrict__ node, const float* __restrict__ edge) {
    int idx = blockIdx.x * 256 + threadIdx.x;
    float v = (idx < NODE_N) ? node[idx] : edge[idx - NODE_N];
    float mn = v, mx = v;
    #pragma unroll
    for (int o = 16; o; o >>= 1) {
        mn = fminf(mn, __shfl_xor_sync(~0u, mn, o));
        mx = fmaxf(mx, __shfl_xor_sync(~0u, mx, o));
    }
    __shared__ float smn[8], smx[8];
    int lane = threadIdx.x & 31, w = threadIdx.x >> 5;
    if (lane == 0) { smn[w] = mn; smx[w] = mx; }
    __syncthreads();
    if (threadIdx.x == 0) {
        float bmn = smn[0], bmx = smx[0];
        #pragma unroll
        for (int i = 1; i < 8; i++) { bmn = fminf(bmn, smn[i]); bmx = fmaxf(bmx, smx[i]); }
        atomicMinF(&g_mn1, bmn); atomicMaxF(&g_mx1, bmx);
    }
}

__global__ void k_prep1(const float* __restrict__ cond1, const float* __restrict__ eps1) {
    int o = blockIdx.x, i = threadIdx.x;        // 512 x 128
    float w = cond1[o * 128 + i];
    float aw = fabsf(w) * 0.1f;
    float u[8];
    #pragma unroll
    for (int b = 0; b < 8; b++)
        u[b] = eps1[b * (H1 * 128) + o * 128 + i] * aw;
    __half bh = __float2half_rn(w);
    float bhf = __half2float(bh);
    __half bl = __float2half_rn(w - bhf);
    float blf = __half2float(bl);
    int isn = (i < 64), il = i & 63;
    if (isn) { g_W1Nbh[o * 64 + il] = bh; g_W1Nbl[o * 64 + il] = bl; }
    else     { g_W1Ebh[o * 64 + il] = bh; g_W1Ebl[o * 64 + il] = bl; }
    #pragma unroll
    for (int b = 0; b < 8; b++) {
        __half nh = __float2half_rn((float)(1 << b) * u[b]);
        if (isn) g_W1Nn[o * 512 + b * 64 + il] = nh;
        else     g_W1En[o * 512 + b * 64 + il] = nh;
    }
    float v7 = 128.f * u[7];
    __half h7 = __float2half_rn(v7);
    __half l7 = __float2half_rn(v7 - __half2float(h7));
    if (isn) g_W1Nn7[o * 64 + il] = l7;
    else     g_W1En7[o * 64 + il] = l7;

    float c = 1024.f * (bhf + blf);
    __shared__ float red[128];
    red[i] = w + u[7]; __syncthreads();
    #pragma unroll
    for (int s = 64; s; s >>= 1) { if (i < s) red[i] += red[i + s]; __syncthreads(); }
    if (i == 0) g_S1[o] = red[0];
    __syncthreads();
    red[i] = isn ? c : 0.f; __syncthreads();
    #pragma unroll
    for (int s = 64; s; s >>= 1) { if (i < s) red[i] += red[i + s]; __syncthreads(); }
    if (i == 0) g_C1N[o] = red[0];
    __syncthreads();
    red[i] = isn ? 0.f : c; __syncthreads();
    #pragma unroll
    for (int s = 64; s; s >>= 1) { if (i < s) red[i] += red[i + s]; __syncthreads(); }
    if (i == 0) g_C1E[o] = red[0];
}

__global__ void k_prep2(const float* __restrict__ cond2, const float* __restrict__ eps2) {
    int o = blockIdx.x, t = threadIdx.x;        // 128 x 256
    float sr = 0.f, cc = 0.f;
    for (int i = t; i < H1; i += 256) {
        float w = cond2[o * H1 + i];
        float aw = fabsf(w) * 0.1f;
        sr += cond2[H2 * H1 + o * H1 + i];
        __half bh = __float2half_rn(w);
        float bhf = __half2float(bh);
        __half bl = __float2half_rn(w - bhf);
        cc += 1024.f * (bhf + __half2float(bl));
        g_W2bh[o * 512 + i] = bh; g_W2bl[o * 512 + i] = bl;
        float u7 = 0.f;
        #pragma unroll
        for (int b = 0; b < 8; b++) {
            float u = eps2[b * (H2 * H1) + o * H1 + i] * aw;
            if (b == 7) u7 = u;
            g_W2n[o * 4096 + b * 512 + i] = __float2half_rn((float)(1 << b) * u);
        }
        float v7 = 128.f * u7;
        __half h7 = __float2half_rn(v7);
        g_W2n7[o * 512 + i] = __float2half_rn(v7 - __half2float(h7));
    }
    __shared__ float red[256];
    red[t] = sr; __syncthreads();
    #pragma unroll
    for (int s = 128; s; s >>= 1) { if (t < s) red[t] += red[t + s]; __syncthreads(); }
    if (t == 0) g_S2[o] = red[0];
    __syncthreads();
    red[t] = cc; __syncthreads();
    #pragma unroll
    for (int s = 128; s; s >>= 1) { if (t < s) red[t] += red[t + s]; __syncthreads(); }
    if (t == 0) g_C2[o] = red[0];
}

// ---------------- GEMM: base (Q+1024, w hi/lo) + noise (bit planes) ----------------
// 32x32 warp tiles (acc=32 regs) + smaller CTA tiles -> 2 CTAs/SM for latency hiding.
// EPI=0: node  M128xN64 tile (M=1536, SC=64)  -> g_zn
// EPI=1: edge  M128xN64 tile (M=18432, SC=64) -> g_h (+zn, relu, minmax)
// EPI=2: layer2 M64xN128 tile (SC=512)        -> g_c2
template<int EPI>
__global__ void __launch_bounds__(256, 2) k_tc(const float* __restrict__ node,
                                               const float* __restrict__ edge) {
    constexpr int SC    = (EPI == 2) ? 512 : 64;
    constexpr int N     = (EPI == 2) ? H2 : H1;
    constexpr int MT    = (EPI == 2) ? 64 : 128;    // CTA m-tile
    constexpr int NTILE = (EPI == 2) ? 128 : 64;    // CTA n-tile
    constexpr int WNC   = (EPI == 2) ? 4 : 2;       // warps along n
    constexpr int SPP   = SC / 64;
    constexpr int NSB   = 2 * SPP;
    constexpr int NSN   = 8 * SPP;
    constexpr int NST   = 11 * SPP;
    constexpr int QROWB = SC + 16;
    constexpr int SROW  = 72;
    constexpr int BTILE = NTILE * SROW;             // halves
    constexpr int ATILE = MT * SROW;                // halves
    const __half* Wbh = (EPI == 0) ? g_W1Nbh : (EPI == 1) ? g_W1Ebh : g_W2bh;
    const __half* Wbl = (EPI == 0) ? g_W1Nbl : (EPI == 1) ? g_W1Ebl : g_W2bl;
    const __half* Wn  = (EPI == 0) ? g_W1Nn  : (EPI == 1) ? g_W1En  : g_W2n;
    const __half* Wn7 = (EPI == 0) ? g_W1Nn7 : (EPI == 1) ? g_W1En7 : g_W2n7;
    const float*  C   = (EPI == 0) ? g_C1N : (EPI == 1) ? g_C1E : g_C2;
    const float*  S   = (EPI == 2) ? g_S2 : g_S1;
    float* out = (EPI == 0) ? g_zn : (EPI == 1) ? g_h : g_c2;

    extern __shared__ char smraw[];
    __half*        bsm   = (__half*)smraw;                     // 3 B tiles
    __half*        asmem = bsm + 3 * BTILE;                    // 2 A tiles
    unsigned char* qs    = (unsigned char*)(asmem + 2 * ATILE); // q slab

    const int tid = threadIdx.x, wid = tid >> 5, lane = tid & 31;
    const int wm = wid / WNC, wn = wid % WNC;
    const int g = lane >> 2, ti2 = (lane & 3) * 2;
    const int m0 = blockIdx.y * MT, n0 = blockIdx.x * NTILE;

    float mn, mx;
    if (EPI == 2) { mn = __int_as_float(g_mn2); mx = __int_as_float(g_mx2); }
    else          { mn = __int_as_float(g_mn1); mx = __int_as_float(g_mx1); }
    float qsc = 255.0f / (mx - mn);

    // ---- phase 1: quantize source slab -> q bytes ----
    constexpr int SEGS = SC / 16;
    #pragma unroll 1
    for (int u = tid; u < MT * SEGS; u += 256) {
        int r = u / SEGS, seg = u % SEGS;
        const float4* p;
        if (EPI == 0)      p = (const float4*)(node + (m0 + r) * FN + seg * 16);
        else if (EPI == 1) p = (const float4*)(edge + (size_t)(m0 + r) * 64 + seg * 16);
        else               p = (const float4*)(g_h + (size_t)(m0 + r) * H1 + seg * 16);
        uint4 o4;
        unsigned* ow = (unsigned*)&o4;
        #pragma unroll
        for (int j = 0; j < 4; j++) {
            float4 v = p[j];
            ow[j] = qz(v.x, mn, qsc) | (qz(v.y, mn, qsc) << 8) |
                    (qz(v.z, mn, qsc) << 16) | (qz(v.w, mn, qsc) << 24);
        }
        *(uint4*)(qs + r * QROWB + seg * 16) = o4;
    }
    __syncthreads();   // q slab complete before any expandA

    // ---- k-loop ----
    float acc[2][4][4];
    #pragma unroll
    for (int a = 0; a < 2; a++)
        #pragma unroll
        for (int b = 0; b < 4; b++)
            #pragma unroll
            for (int c = 0; c < 4; c++) acc[a][b][c] = 0.f;

    auto aidx = [&](int s) { return (s < NSB) ? (s >> 1) : (SPP + s - NSB); };

    auto loadB = [&](int s) {
        const __half* W; int rs, kofs;
        if (s < NSB)            { int j = s >> 1; W = (s & 1) ? Wbl : Wbh; rs = SC;     kofs = j * 64; }
        else if (s < NSB + NSN) { int s2 = s - NSB; W = Wn;                rs = 8 * SC; kofs = s2 * 64; }
        else                    { int s7 = s - NSB - NSN; W = Wn7;         rs = SC;     kofs = s7 * 64; }
        __half* bs = bsm + (s % 3) * BTILE;
        #pragma unroll
        for (int it2 = 0; it2 < NTILE / 32; it2++) {
            int cid = tid + it2 * 256;
            int r = cid >> 3, c = (cid & 7) * 8;
            cp_async16(&bs[r * SROW + c], W + (size_t)(n0 + r) * rs + kofs + c);
        }
        asm volatile("cp.async.commit_group;\n");
    };

    // expand A tile for a-index ai into buffer ai&1 (16-half chunks per thread)
    auto expandA = [&](int ai) {
        __half* as2 = asmem + (ai & 1) * ATILE;
        #pragma unroll 1
        for (int c0 = tid; c0 < MT * 4; c0 += 256) {
            int r = c0 >> 2, sg = c0 & 3;
            uint4* dst = (uint4*)(as2 + r * SROW + sg * 16);
            if (ai < SPP) {
                uint4 a = *(const uint4*)(qs + r * QROWB + ai * 64 + sg * 16);
                uint4 v;
                v.x = __byte_perm(a.x, 0x64646464u, 0x4140); v.y = __byte_perm(a.x, 0x64646464u, 0x4342);
                v.z = __byte_perm(a.y, 0x64646464u, 0x4140); v.w = __byte_perm(a.y, 0x64646464u, 0x4342);
                dst[0] = v;
                v.x = __byte_perm(a.z, 0x64646464u, 0x4140); v.y = __byte_perm(a.z, 0x64646464u, 0x4342);
                v.z = __byte_perm(a.w, 0x64646464u, 0x4140); v.w = __byte_perm(a.w, 0x64646464u, 0x4342);
                dst[1] = v;
            } else {
                int na = ai - SPP;
                int b  = (na < 8 * SPP) ? (na / SPP) : 7;
                int jj = (na < 8 * SPP) ? (na % SPP) : (na - 8 * SPP);
                uint4 a = *(const uint4*)(qs + r * QROWB + jj * 64 + sg * 16);
                unsigned qw[4] = {a.x, a.y, a.z, a.w};
                #pragma unroll
                for (int j = 0; j < 2; j++) {
                    unsigned w0 = qw[2 * j], w1 = qw[2 * j + 1];
                    uint4 v;
                    v.x = ((w0 >> b) & 1u) * 0x3C00u | ((w0 >> (8 + b)) & 1u) * 0x3C000000u;
                    v.y = ((w0 >> (16 + b)) & 1u) * 0x3C00u | ((w0 >> (24 + b)) & 1u) * 0x3C000000u;
                    v.z = ((w1 >> b) & 1u) * 0x3C00u | ((w1 >> (8 + b)) & 1u) * 0x3C000000u;
                    v.w = ((w1 >> (16 + b)) & 1u) * 0x3C00u | ((w1 >> (24 + b)) & 1u) * 0x3C000000u;
                    dst[j] = v;
                }
            }
        }
    };

    const int lm = lane >> 3, lr = lane & 7;
    const int lmbase = (wn * 32 + (lm >> 1) * 8 + lr) * SROW + (lm & 1) * 8;   // B
    const int albase = ((lm & 1) * 8 + lr) * SROW + (lm >> 1) * 8;             // A

    loadB(0);
    loadB(1);
    expandA(0);
    __syncthreads();   // A(0) visible
    #pragma unroll 1
    for (int s = 0; s < NST; s++) {
        if (s + 1 < NST) asm volatile("cp.async.wait_group 1;\n");
        else             asm volatile("cp.async.wait_group 0;\n");
        __syncthreads();                       // prev-iter reads done; B(s) visible
        if (s + 1 < NST && aidx(s + 1) != aidx(s)) expandA(aidx(s + 1));
        if (s + 2 < NST) loadB(s + 2);

        const __half* as2 = asmem + (aidx(s) & 1) * ATILE;
        const __half* bs  = bsm + (s % 3) * BTILE;

        #pragma unroll
        for (int kk = 0; kk < 4; kk++) {
            unsigned af[2][4];
            #pragma unroll
            for (int mt = 0; mt < 2; mt++)
                ldmx4(af[mt][0], af[mt][1], af[mt][2], af[mt][3],
                      as2 + albase + (wm * 32 + mt * 16) * SROW + kk * 16);
            unsigned bq[4][2];
            #pragma unroll
            for (int p = 0; p < 2; p++)
                ldmx4(bq[2 * p][0], bq[2 * p][1], bq[2 * p + 1][0], bq[2 * p + 1][1],
                      bs + lmbase + p * (16 * SROW) + kk * 16);
            #pragma unroll
            for (int mt = 0; mt < 2; mt++)
                #pragma unroll
                for (int nt = 0; nt < 4; nt++)
                    asm volatile(
                        "mma.sync.aligned.m16n8k16.row.col.f32.f16.f16.f32 "
                        "{%0,%1,%2,%3},{%4,%5,%6,%7},{%8,%9},{%0,%1,%2,%3};"
                        : "+f"(acc[mt][nt][0]), "+f"(acc[mt][nt][1]),
                          "+f"(acc[mt][nt][2]), "+f"(acc[mt][nt][3])
                        : "r"(af[mt][0]), "r"(af[mt][1]), "r"(af[mt][2]), "r"(af[mt][3]),
                          "r"(bq[nt][0]), "r"(bq[nt][1]));
        }
    }

    // ---- epilogue ----
    if (EPI == 0) {
        #pragma unroll
        for (int mt = 0; mt < 2; mt++)
            #pragma unroll
            for (int nt = 0; nt < 4; nt++)
                #pragma unroll
                for (int c = 0; c < 4; c++) {
                    int row = m0 + wm * 32 + mt * 16 + g + ((c & 2) << 2);
                    int col = n0 + wn * 32 + nt * 8 + ti2 + (c & 1);
                    out[row * H1 + col] = acc[mt][nt][c] - C[col];
                }
    } else if (EPI == 1) {
        float sc = (mx - mn) * (1.0f / 255.0f);
        float lmn = __int_as_float(0x7f800000), lmx = -lmn;
        #pragma unroll
        for (int mt = 0; mt < 2; mt++)
            #pragma unroll
            for (int nt = 0; nt < 4; nt++)
                #pragma unroll
                for (int c = 0; c < 4; c++) {
                    int row = m0 + wm * 32 + mt * 16 + g + ((c & 2) << 2);
                    int col = n0 + wn * 32 + nt * 8 + ti2 + (c & 1);
                    float z = acc[mt][nt][c] - C[col] + g_zn[(row / NBRN) * H1 + col];
                    float hv = z * sc + mn * S[col];
                    hv = fmaxf(hv, 0.f);
                    out[(size_t)row * N + col] = hv;
                    lmn = fminf(lmn, hv); lmx = fmaxf(lmx, hv);
                }
        #pragma unroll
        for (int o = 16; o; o >>= 1) {
            lmn = fminf(lmn, __shfl_xor_sync(~0u, lmn, o));
            lmx = fmaxf(lmx, __shfl_xor_sync(~0u, lmx, o));
        }
        if (lane == 0) { atomicMinF(&g_mn2, lmn); atomicMaxF(&g_mx2, lmx); }
    } else {
        float sc = (mx - mn) * (1.0f / 255.0f);
        #pragma unroll
        for (int mt = 0; mt < 2; mt++)
            #pragma unroll
            for (int nt = 0; nt < 4; nt++)
                #pragma unroll
                for (int c = 0; c < 4; c++) {
                    int row = m0 + wm * 32 + mt * 16 + g + ((c & 2) << 2);
                    int col = n0 + wn * 32 + nt * 8 + ti2 + (c & 1);
                    out[(size_t)row * N + col] = (acc[mt][nt][c] - C[col]) * sc + mn * S[col];
                }
    }
}

// sigmoid(gate)*tanh(extract)*mask, summed over 12 neighbors
__global__ void k_gate(const float* __restrict__ mask) {
    int idx = blockIdx.x * 256 + threadIdx.x;
    int ba = idx >> 6, j = idx & 63;
    float acc = 0.f;
    #pragma unroll
    for (int nb = 0; nb < NBRN; nb++) {
        int m = ba * NBRN + nb;
        float gv = g_c2[m * H2 + j];
        float ev = g_c2[m * H2 + 64 + j];
        acc += (1.f / (1.f + expf(-gv))) * tanhf(ev) * mask[m];
    }
    g_ns[idx] = acc;
}

// deterministic per-feature BN statistics
__global__ void k_stats() {
    int j = blockIdx.x, t = threadIdx.x;
    __shared__ float red[256];
    __shared__ float mean_s;
    float s = 0.f;
    for (int r = t; r < BA_ROWS; r += 256) s += g_ns[r * FN + j];
    red[t] = s; __syncthreads();
    #pragma unroll
    for (int k = 128; k; k >>= 1) { if (t < k) red[t] += red[t + k]; __syncthreads(); }
    if (t == 0) mean_s = red[0] / (float)BA_ROWS;
    __syncthreads();
    float mean = mean_s, s2 = 0.f;
    for (int r = t; r < BA_ROWS; r += 256) { float d = g_ns[r * FN + j] - mean; s2 += d * d; }
    red[t] = s2; __syncthreads();
    #pragma unroll
    for (int k = 128; k; k >>= 1) { if (t < k) red[t] += red[t + k]; __syncthreads(); }
    if (t == 0) { g_mean[j] = mean; g_var[j] = red[0] / (float)BA_ROWS; }
}

__global__ void k_final(const float* __restrict__ node, const float* __restrict__ gamma,
                        const float* __restrict__ beta, float* __restrict__ out) {
    int idx = blockIdx.x * 256 + threadIdx.x;
    int j = idx & 63;
    float bn = (g_ns[idx] - g_mean[j]) / sqrtf(g_var[j] + 1e-5f) * gamma[j] + beta[j];
    out[idx] = fmaxf(node[idx] + bn, 0.f);
}

// ---------------- launcher ----------------
extern "C" void kernel_launch(void* const* d_in, const int* in_sizes, int n_in,
                              void* d_out, int out_size) {
    const float* node  = (const float*)d_in[0];
    const float* edge  = (const float*)d_in[1];
    const float* maskp = (const float*)d_in[2];
    const float* cond1 = (const float*)d_in[3];
    const float* cond2 = (const float*)d_in[4];
    const float* eps1  = (const float*)d_in[5];
    const float* eps2  = (const float*)d_in[6];
    const float* gamma = (const float*)d_in[7];
    const float* beta  = (const float*)d_in[8];
    float* out = (float*)d_out;

    // smem: 3 B + 2 A tiles + q slab
    const int SMEM01 = (3 * 64 * 72 + 2 * 128 * 72) * 2 + 128 * (64 + 16);   // 74752
    const int SMEM2  = (3 * 128 * 72 + 2 * 64 * 72) * 2 + 64 * (512 + 16);   // 107520
    cudaFuncSetAttribute(k_tc<0>, cudaFuncAttributeMaxDynamicSharedMemorySize, SMEM01);
    cudaFuncSetAttribute(k_tc<1>, cudaFuncAttributeMaxDynamicSharedMemorySize, SMEM01);
    cudaFuncSetAttribute(k_tc<2>, cudaFuncAttributeMaxDynamicSharedMemorySize, SMEM2);

    // order chosen so the ncu capture slot (launch idx 3) lands on k_tc<0>
    k_init<<<1, 1>>>();
    k_minmax<<<(NODE_N + EDGE_N) / 256, 256>>>(node, edge);
    k_prep1<<<H1, 128>>>(cond1, eps1);
    k_tc<0><<<dim3(H1 / 64, BA_ROWS / 128), 256, SMEM01>>>(node, edge);
    k_prep2<<<H2, 256>>>(cond2, eps2);
    k_tc<1><<<dim3(H1 / 64, M_ROWS / 128), 256, SMEM01>>>(node, edge);
    k_tc<2><<<dim3(H2 / 128, M_ROWS / 64), 256, SMEM2>>>(nullptr, nullptr);
    k_gate<<<(BA_ROWS * FN) / 256, 256>>>(maskp);
    k_stats<<<FN, 256>>>();
    k_final<<<(BA_ROWS * FN) / 256, 256>>>(node, gamma, beta, out);
}